// round 12
// baseline (speedup 1.0000x reference)
#include <cuda_runtime.h>
#include <math.h>
#include <stdint.h>

#define NB_   7
#define S_    16
#define D_    128
#define B_    32
#define T_    2048
#define KMAX_ 31

__constant__ int c_ks[NB_] = {31, 21, 15, 11, 7, 5, 3};

// Scratch (device globals; no allocations allowed)
__device__ float g_p[(size_t)B_ * T_ * NB_ * 4 * S_];    // cat layout  [b][t][nb][4S]

// Fragment-major packed tf32 weights (permuted in k_prep)
#define NWC (NB_ * KMAX_ * S_ * D_)      // 444416
#define NW1 (NB_ * D_ * 2 * D_)          // 229376
#define NW2 (NB_ * 2 * D_ * D_)          // 229376
#define NWP (NB_ * D_ * 64)              // 57344
#define NWM (448 * 128)                  // 57344
__device__ float g_wc[NWC];
__device__ float g_w1[NW1];
__device__ float g_w2[NW2];
__device__ float g_wp[NWP];
__device__ float g_wm[NWM];

__device__ __forceinline__ float gelu_exact(float v) {
    return 0.5f * v * (1.0f + erff(v * 0.70710678118654752440f));
}

__device__ __forceinline__ uint32_t f2tf(float f) {
    uint32_t r;
    asm("cvt.rna.tf32.f32 %0, %1;" : "=r"(r) : "f"(f));
    return r;
}
__device__ __forceinline__ float f2tf_f(float f) { return __uint_as_float(f2tf(f)); }

__device__ __forceinline__ void mma_tf32(float c[4],
    uint32_t a0, uint32_t a1, uint32_t a2, uint32_t a3,
    uint32_t b0, uint32_t b1)
{
    asm volatile(
        "mma.sync.aligned.m16n8k8.row.col.f32.tf32.tf32.f32 "
        "{%0,%1,%2,%3},{%4,%5,%6,%7},{%8,%9},{%0,%1,%2,%3};"
        : "+f"(c[0]), "+f"(c[1]), "+f"(c[2]), "+f"(c[3])
        : "r"(a0), "r"(a1), "r"(a2), "r"(a3), "r"(b0), "r"(b1));
}

// ---------------------------------------------------------------------------
// Kernel 0: tf32-round + permute all GEMM weights into fragment-major order.
// ---------------------------------------------------------------------------
__global__ __launch_bounds__(256) void k_prep(
    const float* __restrict__ cw, const float* __restrict__ w1,
    const float* __restrict__ w2, const float* __restrict__ pw,
    const float* __restrict__ mw1)
{
    const int stride = gridDim.x * blockDim.x;
    const int i0 = blockIdx.x * blockDim.x + threadIdx.x;

    for (int i = i0; i < NW1; i += stride) {
        int pair = i & 1, nt = (i >> 1) & 3, lane = (i >> 3) & 31;
        int w = (i >> 8) & 7, kb = (i >> 11) & 15, band = i >> 15;
        int k = kb * 8 + (lane & 3) + pair * 4;
        int col = w * 32 + nt * 8 + (lane >> 2);
        g_w1[i] = f2tf_f(w1[((size_t)band * 128 + k) * 256 + col]);
    }
    for (int i = i0; i < NW2; i += stride) {
        int pair = i & 1, nt = (i >> 1) & 1, lane = (i >> 2) & 31;
        int w = (i >> 7) & 7, kb = (i >> 10) & 31, band = i >> 15;
        int k = kb * 8 + (lane & 3) + pair * 4;
        int col = w * 16 + nt * 8 + (lane >> 2);
        g_w2[i] = f2tf_f(w2[((size_t)band * 256 + k) * 128 + col]);
    }
    for (int i = i0; i < NWP; i += stride) {
        int pair = i & 1, lane = (i >> 1) & 31;
        int w = (i >> 6) & 7, kb = (i >> 9) & 15, band = i >> 13;
        int k = kb * 8 + (lane & 3) + pair * 4;
        int col = w * 8 + (lane >> 2);
        g_wp[i] = f2tf_f(pw[((size_t)band * 128 + k) * 64 + col]);
    }
    for (int i = i0; i < NWC; i += stride) {
        int sub = i & 1023;
        int pair = sub & 1, nt = (sub >> 1) & 1, lane = (sub >> 2) & 31, w = sub >> 7;
        int rest = i >> 10;
        int c8 = rest & 1; rest >>= 1;
        int k = rest % 31, band = rest / 31;
        int s = c8 * 8 + (lane & 3) + pair * 4;
        int col = w * 16 + nt * 8 + (lane >> 2);
        g_wc[i] = f2tf_f(cw[(((size_t)band * 31 + k) * 16 + s) * 128 + col]);
    }
    for (int i = i0; i < NWM; i += stride) {
        int pair = i & 1, nt = (i >> 1) & 1, lane = (i >> 2) & 31;
        int w = (i >> 7) & 7, kb = i >> 10;
        int k = kb * 8 + (lane & 3) + pair * 4;
        int col = w * 16 + nt * 8 + (lane >> 2);
        g_wm[i] = f2tf_f(mw1[(size_t)k * 128 + col]);
    }
}

// ---------------------------------------------------------------------------
// Kernel 1 (FUSED): conv -> LN1 -> LN2 -> GEMM1(gelu) -> GEMM2(+h) -> proj
// grid (T/32, B, NB), block 256, 2 CTAs/SM.
// Depth-4 register double-buffered weight prefetch in every mainloop.
// smem: pool[8320] (xs | us), hs[32*132], zs[32*132]  => 67072 B
// ---------------------------------------------------------------------------
#define XSTR 20
#define HP   132
#define ZP   132
#define UP   260

__global__ __launch_bounds__(256, 2) void k_fused(
    const float* __restrict__ x,
    const float* __restrict__ conv_b,
    const float* __restrict__ dec_g, const float* __restrict__ dec_b,
    const float* __restrict__ n2_g, const float* __restrict__ n2_b,
    const float* __restrict__ fb1, const float* __restrict__ fb2,
    const float* __restrict__ pb)
{
    extern __shared__ float sm[];
    float* pool = sm;               // xs (62*20=1240) then us (32*260=8320)
    float* xs = pool;
    float* us = pool;
    float* hs = sm + 8320;          // 32*132
    float* zs = sm + 12544;         // 32*132

    const int band = blockIdx.z, b = blockIdx.y;
    const int t0 = blockIdx.x * 32;
    const int tid = threadIdx.x;
    const int warp = tid >> 5, lane = tid & 31;
    const int grp = lane >> 2, tig = lane & 3;

    // ---- stage x window rows [t0-15, t0+46], tf32-rounded ----
    const float* xb = x + (size_t)b * T_ * S_;
    for (int i = tid; i < 62 * S_; i += 256) {
        int row = i >> 4, s = i & 15;
        int gt = t0 + row - (KMAX_ / 2);
        float v = (gt >= 0 && gt < T_) ? xb[gt * S_ + s] : 0.0f;
        xs[row * XSTR + s] = f2tf_f(v);
    }
    __syncthreads();

    // ---- conv as mma (masked taps), depth-4 prefetched weights ----
    {
        float acc[2][2][4];
#pragma unroll
        for (int mt = 0; mt < 2; ++mt)
#pragma unroll
            for (int nt = 0; nt < 2; ++nt)
#pragma unroll
                for (int c = 0; c < 4; ++c) acc[mt][nt][c] = 0.0f;

        const int Kb = c_ks[band];
        const int off = (KMAX_ - Kb) >> 1;
        const int steps = 2 * Kb;                       // flattened (k,c8), 6..62
        // lane's weight address for step s: k=off+s/2, c8=s&1
        const float* wc0 = g_wc + ((((size_t)band * 31) * 2) * 8 + warp) * 32 * 4 + lane * 4;
        // index for step s: (((off + (s>>1))*2 + (s&1)) * 8w*32l*4) offset from band base
        auto cw_addr = [&](int s) {
            int k = off + (s >> 1), c8 = s & 1;
            return wc0 + ((size_t)(k * 2 + c8)) * (8 * 32 * 4);
        };

        float4 cwbuf[4];
#pragma unroll
        for (int p = 0; p < 4; ++p)
            cwbuf[p] = (p < steps) ? __ldg((const float4*)cw_addr(p)) : make_float4(0,0,0,0);

        for (int so = 0; so < steps; so += 4) {
#pragma unroll
            for (int u = 0; u < 4; ++u) {
                int s = so + u;
                if (s < steps) {
                    const int k = off + (s >> 1);
                    const int s0 = (s & 1) * 8;
                    float4 wv = cwbuf[u];
                    if (s + 4 < steps) cwbuf[u] = __ldg((const float4*)cw_addr(s + 4));
                    uint32_t a[2][4];
#pragma unroll
                    for (int mt = 0; mt < 2; ++mt) {
                        int r0 = mt * 16 + grp + k;
                        a[mt][0] = __float_as_uint(xs[r0 * XSTR + s0 + tig]);
                        a[mt][1] = __float_as_uint(xs[(r0 + 8) * XSTR + s0 + tig]);
                        a[mt][2] = __float_as_uint(xs[r0 * XSTR + s0 + tig + 4]);
                        a[mt][3] = __float_as_uint(xs[(r0 + 8) * XSTR + s0 + tig + 4]);
                    }
#pragma unroll
                    for (int nt = 0; nt < 2; ++nt) {
                        uint32_t bf0 = __float_as_uint(nt ? wv.z : wv.x);
                        uint32_t bf1 = __float_as_uint(nt ? wv.w : wv.y);
#pragma unroll
                        for (int mt = 0; mt < 2; ++mt)
                            mma_tf32(acc[mt][nt], a[mt][0], a[mt][1], a[mt][2], a[mt][3], bf0, bf1);
                    }
                }
            }
        }

        // bias -> hs (pre-LN conv output)
#pragma unroll
        for (int nt = 0; nt < 2; ++nt) {
            int col0 = warp * 16 + nt * 8 + tig * 2;
            float bb0 = conv_b[band * D_ + col0];
            float bb1 = conv_b[band * D_ + col0 + 1];
#pragma unroll
            for (int mt = 0; mt < 2; ++mt) {
                int r0 = mt * 16 + grp;
                hs[r0 * HP + col0]           = acc[mt][nt][0] + bb0;
                hs[r0 * HP + col0 + 1]       = acc[mt][nt][1] + bb1;
                hs[(r0 + 8) * HP + col0]     = acc[mt][nt][2] + bb0;
                hs[(r0 + 8) * HP + col0 + 1] = acc[mt][nt][3] + bb1;
            }
        }
    }
    __syncthreads();   // hs complete; xs dead from here (pool becomes us)

    // ---- combined LN1 + LN2: hs := h, zs := tf32(z). warp = 4 tokens ----
    {
        float g1v[4], b1v[4], g2v[4], b2v[4];
#pragma unroll
        for (int c = 0; c < 4; ++c) {
            g1v[c] = dec_g[band * D_ + lane + 32 * c];
            b1v[c] = dec_b[band * D_ + lane + 32 * c];
            g2v[c] = n2_g[band * D_ + lane + 32 * c];
            b2v[c] = n2_b[band * D_ + lane + 32 * c];
        }
        for (int i = 0; i < 4; ++i) {
            int tt = warp * 4 + i;
            float v[4]; float s = 0.0f;
#pragma unroll
            for (int c = 0; c < 4; ++c) { v[c] = hs[tt * HP + lane + 32 * c]; s += v[c]; }
#pragma unroll
            for (int o = 16; o; o >>= 1) s += __shfl_xor_sync(0xffffffffu, s, o);
            float mean = s * (1.0f / 128.0f);
            float q = 0.0f;
#pragma unroll
            for (int c = 0; c < 4; ++c) { float d0 = v[c] - mean; q = fmaf(d0, d0, q); }
#pragma unroll
            for (int o = 16; o; o >>= 1) q += __shfl_xor_sync(0xffffffffu, q, o);
            float rstd = rsqrtf(q * (1.0f / 128.0f) + 1e-5f);

            float hv[4]; float s2 = 0.0f;
#pragma unroll
            for (int c = 0; c < 4; ++c) {
                hv[c] = (v[c] - mean) * rstd * g1v[c] + b1v[c];
                hs[tt * HP + lane + 32 * c] = hv[c];
                s2 += hv[c];
            }
#pragma unroll
            for (int o = 16; o; o >>= 1) s2 += __shfl_xor_sync(0xffffffffu, s2, o);
            float mean2 = s2 * (1.0f / 128.0f);
            float q2 = 0.0f;
#pragma unroll
            for (int c = 0; c < 4; ++c) { float d0 = hv[c] - mean2; q2 = fmaf(d0, d0, q2); }
#pragma unroll
            for (int o = 16; o; o >>= 1) q2 += __shfl_xor_sync(0xffffffffu, q2, o);
            float rstd2 = rsqrtf(q2 * (1.0f / 128.0f) + 1e-5f);
#pragma unroll
            for (int c = 0; c < 4; ++c)
                zs[tt * ZP + lane + 32 * c] = f2tf_f((hv[c] - mean2) * rstd2 * g2v[c] + b2v[c]);
        }
    }
    __syncthreads();

    // ---- GEMM1: u = gelu(z @ W1 + b1). depth-4 prefetch, warp n-slice 32 ----
    {
        float acc[2][4][4];
#pragma unroll
        for (int mt = 0; mt < 2; ++mt)
#pragma unroll
            for (int nt = 0; nt < 4; ++nt)
#pragma unroll
                for (int c = 0; c < 4; ++c) acc[mt][nt][c] = 0.0f;

        const float* wbase = g_w1 + ((((size_t)band * 16) * 8 + warp) * 32 + lane) * 8;
        float4 wbuf[4][2];
#pragma unroll
        for (int p = 0; p < 4; ++p) {
            wbuf[p][0] = __ldg((const float4*)(wbase + (size_t)p * 2048));
            wbuf[p][1] = __ldg((const float4*)(wbase + (size_t)p * 2048 + 4));
        }
#pragma unroll
        for (int kbo = 0; kbo < 16; kbo += 4) {
#pragma unroll
            for (int u = 0; u < 4; ++u) {
                const int kb = kbo + u;
                const int k0 = kb * 8;
                float4 w0 = wbuf[u][0], w1v = wbuf[u][1];
                if (kb + 4 < 16) {
                    wbuf[u][0] = __ldg((const float4*)(wbase + (size_t)(kb + 4) * 2048));
                    wbuf[u][1] = __ldg((const float4*)(wbase + (size_t)(kb + 4) * 2048 + 4));
                }
                uint32_t a[2][4];
#pragma unroll
                for (int mt = 0; mt < 2; ++mt) {
                    int r0 = mt * 16 + grp;
                    a[mt][0] = __float_as_uint(zs[r0 * ZP + k0 + tig]);
                    a[mt][1] = __float_as_uint(zs[(r0 + 8) * ZP + k0 + tig]);
                    a[mt][2] = __float_as_uint(zs[r0 * ZP + k0 + tig + 4]);
                    a[mt][3] = __float_as_uint(zs[(r0 + 8) * ZP + k0 + tig + 4]);
                }
                const float wv[8] = {w0.x, w0.y, w0.z, w0.w, w1v.x, w1v.y, w1v.z, w1v.w};
#pragma unroll
                for (int nt = 0; nt < 4; ++nt) {
                    uint32_t bf0 = __float_as_uint(wv[nt * 2]);
                    uint32_t bf1 = __float_as_uint(wv[nt * 2 + 1]);
#pragma unroll
                    for (int mt = 0; mt < 2; ++mt)
                        mma_tf32(acc[mt][nt], a[mt][0], a[mt][1], a[mt][2], a[mt][3], bf0, bf1);
                }
            }
        }
#pragma unroll
        for (int nt = 0; nt < 4; ++nt) {
            int col0 = warp * 32 + nt * 8 + tig * 2;
            float bb0 = fb1[band * 256 + col0];
            float bb1 = fb1[band * 256 + col0 + 1];
#pragma unroll
            for (int mt = 0; mt < 2; ++mt) {
                int r0 = mt * 16 + grp;
                us[r0 * UP + col0]           = f2tf_f(gelu_exact(acc[mt][nt][0] + bb0));
                us[r0 * UP + col0 + 1]       = f2tf_f(gelu_exact(acc[mt][nt][1] + bb1));
                us[(r0 + 8) * UP + col0]     = f2tf_f(gelu_exact(acc[mt][nt][2] + bb0));
                us[(r0 + 8) * UP + col0 + 1] = f2tf_f(gelu_exact(acc[mt][nt][3] + bb1));
            }
        }
    }
    __syncthreads();

    // ---- GEMM2: band_out = h + u @ W2 + b2 -> zs. depth-4 prefetch ----
    {
        float acc[2][2][4];
#pragma unroll
        for (int mt = 0; mt < 2; ++mt)
#pragma unroll
            for (int nt = 0; nt < 2; ++nt)
#pragma unroll
                for (int c = 0; c < 4; ++c) acc[mt][nt][c] = 0.0f;

        const float* wbase = g_w2 + ((((size_t)band * 32) * 8 + warp) * 32 + lane) * 4;
        float4 wbuf[4];
#pragma unroll
        for (int p = 0; p < 4; ++p)
            wbuf[p] = __ldg((const float4*)(wbase + (size_t)p * 1024));
#pragma unroll
        for (int kbo = 0; kbo < 32; kbo += 4) {
#pragma unroll
            for (int u = 0; u < 4; ++u) {
                const int kb = kbo + u;
                const int k0 = kb * 8;
                float4 wv = wbuf[u];
                if (kb + 4 < 32)
                    wbuf[u] = __ldg((const float4*)(wbase + (size_t)(kb + 4) * 1024));
                uint32_t a[2][4];
#pragma unroll
                for (int mt = 0; mt < 2; ++mt) {
                    int r0 = mt * 16 + grp;
                    a[mt][0] = __float_as_uint(us[r0 * UP + k0 + tig]);
                    a[mt][1] = __float_as_uint(us[(r0 + 8) * UP + k0 + tig]);
                    a[mt][2] = __float_as_uint(us[r0 * UP + k0 + tig + 4]);
                    a[mt][3] = __float_as_uint(us[(r0 + 8) * UP + k0 + tig + 4]);
                }
#pragma unroll
                for (int nt = 0; nt < 2; ++nt) {
                    uint32_t bf0 = __float_as_uint(nt ? wv.z : wv.x);
                    uint32_t bf1 = __float_as_uint(nt ? wv.w : wv.y);
#pragma unroll
                    for (int mt = 0; mt < 2; ++mt)
                        mma_tf32(acc[mt][nt], a[mt][0], a[mt][1], a[mt][2], a[mt][3], bf0, bf1);
                }
            }
        }
#pragma unroll
        for (int nt = 0; nt < 2; ++nt) {
            int col0 = warp * 16 + nt * 8 + tig * 2;
            float bb0 = fb2[band * 128 + col0];
            float bb1 = fb2[band * 128 + col0 + 1];
#pragma unroll
            for (int mt = 0; mt < 2; ++mt) {
                int r0 = mt * 16 + grp;
                zs[r0 * ZP + col0]           = f2tf_f(acc[mt][nt][0] + bb0 + hs[r0 * HP + col0]);
                zs[r0 * ZP + col0 + 1]       = f2tf_f(acc[mt][nt][1] + bb1 + hs[r0 * HP + col0 + 1]);
                zs[(r0 + 8) * ZP + col0]     = f2tf_f(acc[mt][nt][2] + bb0 + hs[(r0 + 8) * HP + col0]);
                zs[(r0 + 8) * ZP + col0 + 1] = f2tf_f(acc[mt][nt][3] + bb1 + hs[(r0 + 8) * HP + col0 + 1]);
            }
        }
    }
    __syncthreads();

    // ---- proj: p = band_out @ pw + pb -> g_p (tf32). depth-4 prefetch ----
    {
        float acc[2][4];
#pragma unroll
        for (int mt = 0; mt < 2; ++mt)
#pragma unroll
            for (int c = 0; c < 4; ++c) acc[mt][c] = 0.0f;

        const float* wbase = g_wp + ((((size_t)band * 16) * 8 + warp) * 32 + lane) * 2;
        float2 wbuf[4];
#pragma unroll
        for (int p = 0; p < 4; ++p)
            wbuf[p] = __ldg((const float2*)(wbase + (size_t)p * 512));
#pragma unroll
        for (int kbo = 0; kbo < 16; kbo += 4) {
#pragma unroll
            for (int u = 0; u < 4; ++u) {
                const int kb = kbo + u;
                const int k0 = kb * 8;
                float2 wv = wbuf[u];
                if (kb + 4 < 16)
                    wbuf[u] = __ldg((const float2*)(wbase + (size_t)(kb + 4) * 512));
                uint32_t a[2][4];
#pragma unroll
                for (int mt = 0; mt < 2; ++mt) {
                    int r0 = mt * 16 + grp;
                    a[mt][0] = __float_as_uint(zs[r0 * ZP + k0 + tig]);
                    a[mt][1] = __float_as_uint(zs[(r0 + 8) * ZP + k0 + tig]);
                    a[mt][2] = __float_as_uint(zs[r0 * ZP + k0 + tig + 4]);
                    a[mt][3] = __float_as_uint(zs[(r0 + 8) * ZP + k0 + tig + 4]);
                }
                uint32_t bf0 = __float_as_uint(wv.x);
                uint32_t bf1 = __float_as_uint(wv.y);
#pragma unroll
                for (int mt = 0; mt < 2; ++mt)
                    mma_tf32(acc[mt], a[mt][0], a[mt][1], a[mt][2], a[mt][3], bf0, bf1);
            }
        }
        int col0 = warp * 8 + tig * 2;
        float bb0 = pb[band * 64 + col0];
        float bb1 = pb[band * 64 + col0 + 1];
#pragma unroll
        for (int mt = 0; mt < 2; ++mt) {
            int r0 = mt * 16 + grp;
            float2 v0 = make_float2(f2tf_f(acc[mt][0] + bb0), f2tf_f(acc[mt][1] + bb1));
            float2 v1 = make_float2(f2tf_f(acc[mt][2] + bb0), f2tf_f(acc[mt][3] + bb1));
            *(float2*)&g_p[(((size_t)b * T_ + t0 + r0) * NB_ + band) * 64 + col0] = v0;
            *(float2*)&g_p[(((size_t)b * T_ + t0 + r0 + 8) * NB_ + band) * 64 + col0] = v1;
        }
    }
}

// ---------------------------------------------------------------------------
// Kernel 3 (tensor-core GEMM1): cat[32,448] @ mix_w1 -> gelu -> fp32 128->16.
// Depth-4 weight prefetch. grid (B*T/32), block 256.
// ---------------------------------------------------------------------------
#define CP 452
#define MP 132

__global__ __launch_bounds__(256, 2) void k_mix_tc(
    const float* __restrict__ mb1,
    const float* __restrict__ mw2, const float* __restrict__ mb2,
    float* __restrict__ out)
{
    extern __shared__ float sm[];
    float* cs = sm;                 // 32*452
    float* ms = sm + 32 * CP;       // 32*132

    const int bt0 = blockIdx.x * 32;
    const int tid = threadIdx.x;
    const int warp = tid >> 5, lane = tid & 31;
    const int grp = lane >> 2, tig = lane & 3;

    const float* cb = g_p + (size_t)bt0 * 448;
    for (int i = tid; i < 32 * 448; i += 256) {
        int r = i / 448, c = i - r * 448;
        cs[r * CP + c] = cb[i];
    }
    __syncthreads();

    {
        float acc[2][2][4];
#pragma unroll
        for (int mt = 0; mt < 2; ++mt)
#pragma unroll
            for (int nt = 0; nt < 2; ++nt)
#pragma unroll
                for (int c = 0; c < 4; ++c) acc[mt][nt][c] = 0.0f;

        const float* wbase = g_wm + ((size_t)warp * 32 + lane) * 4;
        float4 wbuf[4];
#pragma unroll
        for (int p = 0; p < 4; ++p)
            wbuf[p] = __ldg((const float4*)(wbase + (size_t)p * 1024));

        for (int kbo = 0; kbo < 56; kbo += 4) {
#pragma unroll
            for (int u = 0; u < 4; ++u) {
                const int kb = kbo + u;
                const int k0 = kb * 8;
                float4 wv = wbuf[u];
                if (kb + 4 < 56)
                    wbuf[u] = __ldg((const float4*)(wbase + (size_t)(kb + 4) * 1024));
                uint32_t a[2][4];
#pragma unroll
                for (int mt = 0; mt < 2; ++mt) {
                    int r0 = mt * 16 + grp;
                    a[mt][0] = __float_as_uint(cs[r0 * CP + k0 + tig]);
                    a[mt][1] = __float_as_uint(cs[(r0 + 8) * CP + k0 + tig]);
                    a[mt][2] = __float_as_uint(cs[r0 * CP + k0 + tig + 4]);
                    a[mt][3] = __float_as_uint(cs[(r0 + 8) * CP + k0 + tig + 4]);
                }
#pragma unroll
                for (int nt = 0; nt < 2; ++nt) {
                    uint32_t bf0 = __float_as_uint(nt ? wv.z : wv.x);
                    uint32_t bf1 = __float_as_uint(nt ? wv.w : wv.y);
#pragma unroll
                    for (int mt = 0; mt < 2; ++mt)
                        mma_tf32(acc[mt][nt], a[mt][0], a[mt][1], a[mt][2], a[mt][3], bf0, bf1);
                }
            }
        }
#pragma unroll
        for (int nt = 0; nt < 2; ++nt) {
            int col0 = warp * 16 + nt * 8 + tig * 2;
            float bb0 = mb1[col0];
            float bb1 = mb1[col0 + 1];
#pragma unroll
            for (int mt = 0; mt < 2; ++mt) {
                int r0 = mt * 16 + grp;
                ms[r0 * MP + col0]           = gelu_exact(acc[mt][nt][0] + bb0);
                ms[r0 * MP + col0 + 1]       = gelu_exact(acc[mt][nt][1] + bb1);
                ms[(r0 + 8) * MP + col0]     = gelu_exact(acc[mt][nt][2] + bb0);
                ms[(r0 + 8) * MP + col0 + 1] = gelu_exact(acc[mt][nt][3] + bb1);
            }
        }
    }
    __syncthreads();

    {
        const int o = tid & 15, tb = tid >> 4;
        const float* wc = mw2 + o;
        const float bo = mb2[o];
#pragma unroll
        for (int h = 0; h < 2; ++h) {
            int tt = tb + h * 16;
            float acc = 0.0f;
            for (int e = 0; e < 128; e += 4) {
                float4 mv = *(const float4*)&ms[tt * MP + e];
                acc = fmaf(mv.x, wc[(e + 0) * 16], acc);
                acc = fmaf(mv.y, wc[(e + 1) * 16], acc);
                acc = fmaf(mv.z, wc[(e + 2) * 16], acc);
                acc = fmaf(mv.w, wc[(e + 3) * 16], acc);
            }
            out[(size_t)(bt0 + tt) * 16 + o] = acc + bo;
        }
    }
}

// ---------------------------------------------------------------------------
extern "C" void kernel_launch(void* const* d_in, const int* in_sizes, int n_in,
                              void* d_out, int out_size)
{
    const float* x      = (const float*)d_in[0];
    const float* conv_w = (const float*)d_in[1];
    const float* conv_b = (const float*)d_in[2];
    const float* dec_g  = (const float*)d_in[3];
    const float* dec_b  = (const float*)d_in[4];
    const float* n2_g   = (const float*)d_in[5];
    const float* n2_b   = (const float*)d_in[6];
    const float* ffn_w1 = (const float*)d_in[7];
    const float* ffn_b1 = (const float*)d_in[8];
    const float* ffn_w2 = (const float*)d_in[9];
    const float* ffn_b2 = (const float*)d_in[10];
    const float* proj_w = (const float*)d_in[11];
    const float* proj_b = (const float*)d_in[12];
    const float* mix_w1 = (const float*)d_in[13];
    const float* mix_b1 = (const float*)d_in[14];
    const float* mix_w2 = (const float*)d_in[15];
    const float* mix_b2 = (const float*)d_in[16];
    float* out = (float*)d_out;

    const int smem_fused = (8320 + 4224 + 4224) * 4;        // 67072 B
    const int smem_mix   = (32 * CP + 32 * MP) * 4;         // 74752 B
    cudaFuncSetAttribute(k_fused, cudaFuncAttributeMaxDynamicSharedMemorySize, smem_fused);
    cudaFuncSetAttribute(k_mix_tc, cudaFuncAttributeMaxDynamicSharedMemorySize, smem_mix);

    k_prep<<<512, 256>>>(conv_w, ffn_w1, ffn_w2, proj_w, mix_w1);

    dim3 g1(T_ / 32, B_, NB_);
    k_fused<<<g1, 256, smem_fused>>>(x, conv_b, dec_g, dec_b, n2_g, n2_b,
                                     ffn_b1, ffn_b2, proj_b);

    dim3 g3((B_ * T_) / 32);
    k_mix_tc<<<g3, 256, smem_mix>>>(mix_b1, mix_w2, mix_b2, out);
}

// round 13
// speedup vs baseline: 1.2014x; 1.2014x over previous
#include <cuda_runtime.h>
#include <math.h>
#include <stdint.h>

#define NB_   7
#define S_    16
#define D_    128
#define B_    32
#define T_    2048
#define KMAX_ 31

__constant__ int c_ks[NB_] = {31, 21, 15, 11, 7, 5, 3};

// Scratch (device globals; no allocations allowed)
__device__ float g_p[(size_t)B_ * T_ * NB_ * 4 * S_];    // cat layout  [b][t][nb][4S]

// Fragment-major packed tf32 weights (permuted in k_prep)
#define NWC (NB_ * KMAX_ * S_ * D_)      // 444416
#define NW1 (NB_ * D_ * 2 * D_)          // 229376
#define NW2 (NB_ * 2 * D_ * D_)          // 229376
#define NWP (NB_ * D_ * 64)              // 57344
#define NWM (448 * 128)                  // 57344
__device__ float g_wc[NWC];
__device__ float g_w1[NW1];
__device__ float g_w2[NW2];
__device__ float g_wp[NWP];
__device__ float g_wm[NWM];

__device__ __forceinline__ float gelu_exact(float v) {
    return 0.5f * v * (1.0f + erff(v * 0.70710678118654752440f));
}

__device__ __forceinline__ uint32_t f2tf(float f) {
    uint32_t r;
    asm("cvt.rna.tf32.f32 %0, %1;" : "=r"(r) : "f"(f));
    return r;
}
__device__ __forceinline__ float f2tf_f(float f) { return __uint_as_float(f2tf(f)); }

__device__ __forceinline__ void mma_tf32(float c[4],
    uint32_t a0, uint32_t a1, uint32_t a2, uint32_t a3,
    uint32_t b0, uint32_t b1)
{
    asm volatile(
        "mma.sync.aligned.m16n8k8.row.col.f32.tf32.tf32.f32 "
        "{%0,%1,%2,%3},{%4,%5,%6,%7},{%8,%9},{%0,%1,%2,%3};"
        : "+f"(c[0]), "+f"(c[1]), "+f"(c[2]), "+f"(c[3])
        : "r"(a0), "r"(a1), "r"(a2), "r"(a3), "r"(b0), "r"(b1));
}

// ---------------------------------------------------------------------------
// Kernel 0: tf32-round + permute all GEMM weights into fragment-major order.
// ---------------------------------------------------------------------------
__global__ __launch_bounds__(256) void k_prep(
    const float* __restrict__ cw, const float* __restrict__ w1,
    const float* __restrict__ w2, const float* __restrict__ pw,
    const float* __restrict__ mw1)
{
    const int stride = gridDim.x * blockDim.x;
    const int i0 = blockIdx.x * blockDim.x + threadIdx.x;

    for (int i = i0; i < NW1; i += stride) {
        int pair = i & 1, nt = (i >> 1) & 3, lane = (i >> 3) & 31;
        int w = (i >> 8) & 7, kb = (i >> 11) & 15, band = i >> 15;
        int k = kb * 8 + (lane & 3) + pair * 4;
        int col = w * 32 + nt * 8 + (lane >> 2);
        g_w1[i] = f2tf_f(w1[((size_t)band * 128 + k) * 256 + col]);
    }
    for (int i = i0; i < NW2; i += stride) {
        int pair = i & 1, nt = (i >> 1) & 1, lane = (i >> 2) & 31;
        int w = (i >> 7) & 7, kb = (i >> 10) & 31, band = i >> 15;
        int k = kb * 8 + (lane & 3) + pair * 4;
        int col = w * 16 + nt * 8 + (lane >> 2);
        g_w2[i] = f2tf_f(w2[((size_t)band * 256 + k) * 128 + col]);
    }
    for (int i = i0; i < NWP; i += stride) {
        int pair = i & 1, lane = (i >> 1) & 31;
        int w = (i >> 6) & 7, kb = (i >> 9) & 15, band = i >> 13;
        int k = kb * 8 + (lane & 3) + pair * 4;
        int col = w * 8 + (lane >> 2);
        g_wp[i] = f2tf_f(pw[((size_t)band * 128 + k) * 64 + col]);
    }
    for (int i = i0; i < NWC; i += stride) {
        int sub = i & 1023;
        int pair = sub & 1, nt = (sub >> 1) & 1, lane = (sub >> 2) & 31, w = sub >> 7;
        int rest = i >> 10;
        int c8 = rest & 1; rest >>= 1;
        int k = rest % 31, band = rest / 31;
        int s = c8 * 8 + (lane & 3) + pair * 4;
        int col = w * 16 + nt * 8 + (lane >> 2);
        g_wc[i] = f2tf_f(cw[(((size_t)band * 31 + k) * 16 + s) * 128 + col]);
    }
    for (int i = i0; i < NWM; i += stride) {
        int pair = i & 1, nt = (i >> 1) & 1, lane = (i >> 2) & 31;
        int w = (i >> 7) & 7, kb = i >> 10;
        int k = kb * 8 + (lane & 3) + pair * 4;
        int col = w * 16 + nt * 8 + (lane >> 2);
        g_wm[i] = f2tf_f(mw1[(size_t)k * 128 + col]);
    }
}

// ---------------------------------------------------------------------------
// Kernel 1 (FUSED): conv -> LN1 -> LN2 -> GEMM1(gelu) -> GEMM2(+h) -> proj
// grid (T/32, B, NB), block 256. Fully-unrolled GEMM k-loops (imm offsets).
// smem: pool[8320] (xs | us), hs[32*132], zs[32*132]  => 67072 B
// ---------------------------------------------------------------------------
#define XSTR 20
#define HP   132
#define ZP   132
#define UP   260

__global__ __launch_bounds__(256) void k_fused(
    const float* __restrict__ x,
    const float* __restrict__ conv_b,
    const float* __restrict__ dec_g, const float* __restrict__ dec_b,
    const float* __restrict__ n2_g, const float* __restrict__ n2_b,
    const float* __restrict__ fb1, const float* __restrict__ fb2,
    const float* __restrict__ pb)
{
    extern __shared__ float sm[];
    float* pool = sm;               // xs (62*20=1240) then us (32*260=8320)
    float* xs = pool;
    float* us = pool;
    float* hs = sm + 8320;          // 32*132
    float* zs = sm + 12544;         // 32*132

    const int band = blockIdx.z, b = blockIdx.y;
    const int t0 = blockIdx.x * 32;
    const int tid = threadIdx.x;
    const int warp = tid >> 5, lane = tid & 31;
    const int grp = lane >> 2, tig = lane & 3;

    // ---- stage x window rows [t0-15, t0+46], tf32-rounded ----
    const float* xb = x + (size_t)b * T_ * S_;
    for (int i = tid; i < 62 * S_; i += 256) {
        int row = i >> 4, s = i & 15;
        int gt = t0 + row - (KMAX_ / 2);
        float v = (gt >= 0 && gt < T_) ? xb[gt * S_ + s] : 0.0f;
        xs[row * XSTR + s] = f2tf_f(v);
    }
    __syncthreads();

    // ---- conv as mma (masked taps), packed B float4 loads  [R10 form] ----
    {
        float acc[2][2][4];
#pragma unroll
        for (int mt = 0; mt < 2; ++mt)
#pragma unroll
            for (int nt = 0; nt < 2; ++nt)
#pragma unroll
                for (int c = 0; c < 4; ++c) acc[mt][nt][c] = 0.0f;

        const int Kb = c_ks[band];
        const int off = (KMAX_ - Kb) >> 1;

        for (int k = off; k < off + Kb; ++k) {
#pragma unroll
            for (int c8 = 0; c8 < 2; ++c8) {
                const int s0 = c8 * 8;
                uint32_t a[2][4];
#pragma unroll
                for (int mt = 0; mt < 2; ++mt) {
                    int r0 = mt * 16 + grp + k;
                    a[mt][0] = __float_as_uint(xs[r0 * XSTR + s0 + tig]);
                    a[mt][1] = __float_as_uint(xs[(r0 + 8) * XSTR + s0 + tig]);
                    a[mt][2] = __float_as_uint(xs[r0 * XSTR + s0 + tig + 4]);
                    a[mt][3] = __float_as_uint(xs[(r0 + 8) * XSTR + s0 + tig + 4]);
                }
                const float4 wv = __ldg((const float4*)&g_wc[
                    (((((size_t)band * 31 + k) * 2 + c8) * 8 + warp) * 32 + lane) * 4]);
#pragma unroll
                for (int nt = 0; nt < 2; ++nt) {
                    uint32_t bf0 = __float_as_uint(nt ? wv.z : wv.x);
                    uint32_t bf1 = __float_as_uint(nt ? wv.w : wv.y);
#pragma unroll
                    for (int mt = 0; mt < 2; ++mt)
                        mma_tf32(acc[mt][nt], a[mt][0], a[mt][1], a[mt][2], a[mt][3], bf0, bf1);
                }
            }
        }

        // bias -> hs (pre-LN conv output)
#pragma unroll
        for (int nt = 0; nt < 2; ++nt) {
            int col0 = warp * 16 + nt * 8 + tig * 2;
            float bb0 = conv_b[band * D_ + col0];
            float bb1 = conv_b[band * D_ + col0 + 1];
#pragma unroll
            for (int mt = 0; mt < 2; ++mt) {
                int r0 = mt * 16 + grp;
                hs[r0 * HP + col0]           = acc[mt][nt][0] + bb0;
                hs[r0 * HP + col0 + 1]       = acc[mt][nt][1] + bb1;
                hs[(r0 + 8) * HP + col0]     = acc[mt][nt][2] + bb0;
                hs[(r0 + 8) * HP + col0 + 1] = acc[mt][nt][3] + bb1;
            }
        }
    }
    __syncthreads();   // hs complete; xs dead from here (pool becomes us)

    // ---- combined LN1 + LN2: hs := h, zs := tf32(z). warp = 4 tokens ----
    {
        float g1v[4], b1v[4], g2v[4], b2v[4];
#pragma unroll
        for (int c = 0; c < 4; ++c) {
            g1v[c] = dec_g[band * D_ + lane + 32 * c];
            b1v[c] = dec_b[band * D_ + lane + 32 * c];
            g2v[c] = n2_g[band * D_ + lane + 32 * c];
            b2v[c] = n2_b[band * D_ + lane + 32 * c];
        }
        for (int i = 0; i < 4; ++i) {
            int tt = warp * 4 + i;
            float v[4]; float s = 0.0f;
#pragma unroll
            for (int c = 0; c < 4; ++c) { v[c] = hs[tt * HP + lane + 32 * c]; s += v[c]; }
#pragma unroll
            for (int o = 16; o; o >>= 1) s += __shfl_xor_sync(0xffffffffu, s, o);
            float mean = s * (1.0f / 128.0f);
            float q = 0.0f;
#pragma unroll
            for (int c = 0; c < 4; ++c) { float d0 = v[c] - mean; q = fmaf(d0, d0, q); }
#pragma unroll
            for (int o = 16; o; o >>= 1) q += __shfl_xor_sync(0xffffffffu, q, o);
            float rstd = rsqrtf(q * (1.0f / 128.0f) + 1e-5f);

            float hv[4]; float s2 = 0.0f;
#pragma unroll
            for (int c = 0; c < 4; ++c) {
                hv[c] = (v[c] - mean) * rstd * g1v[c] + b1v[c];
                hs[tt * HP + lane + 32 * c] = hv[c];
                s2 += hv[c];
            }
#pragma unroll
            for (int o = 16; o; o >>= 1) s2 += __shfl_xor_sync(0xffffffffu, s2, o);
            float mean2 = s2 * (1.0f / 128.0f);
            float q2 = 0.0f;
#pragma unroll
            for (int c = 0; c < 4; ++c) { float d0 = hv[c] - mean2; q2 = fmaf(d0, d0, q2); }
#pragma unroll
            for (int o = 16; o; o >>= 1) q2 += __shfl_xor_sync(0xffffffffu, q2, o);
            float rstd2 = rsqrtf(q2 * (1.0f / 128.0f) + 1e-5f);
#pragma unroll
            for (int c = 0; c < 4; ++c)
                zs[tt * ZP + lane + 32 * c] = f2tf_f((hv[c] - mean2) * rstd2 * g2v[c] + b2v[c]);
        }
    }
    __syncthreads();

    // ---- GEMM1: u = gelu(z @ W1 + b1). FULL unroll (imm offsets) ----
    {
        float acc[2][4][4];
#pragma unroll
        for (int mt = 0; mt < 2; ++mt)
#pragma unroll
            for (int nt = 0; nt < 4; ++nt)
#pragma unroll
                for (int c = 0; c < 4; ++c) acc[mt][nt][c] = 0.0f;

        const float* wbase = g_w1 + ((((size_t)band * 16) * 8 + warp) * 32 + lane) * 8;
        const float* z0 = zs + grp * ZP + tig;         // base for A-frag addressing
#pragma unroll
        for (int kb = 0; kb < 16; ++kb) {
            const int k0 = kb * 8;
            uint32_t a[2][4];
#pragma unroll
            for (int mt = 0; mt < 2; ++mt) {
                const float* zm = z0 + mt * 16 * ZP + k0;
                a[mt][0] = __float_as_uint(zm[0]);
                a[mt][1] = __float_as_uint(zm[8 * ZP]);
                a[mt][2] = __float_as_uint(zm[4]);
                a[mt][3] = __float_as_uint(zm[8 * ZP + 4]);
            }
            const float4 w0 = __ldg((const float4*)(wbase + (size_t)kb * 2048));
            const float4 w1v = __ldg((const float4*)(wbase + (size_t)kb * 2048 + 4));
            const float wv[8] = {w0.x, w0.y, w0.z, w0.w, w1v.x, w1v.y, w1v.z, w1v.w};
#pragma unroll
            for (int nt = 0; nt < 4; ++nt) {
                uint32_t bf0 = __float_as_uint(wv[nt * 2]);
                uint32_t bf1 = __float_as_uint(wv[nt * 2 + 1]);
#pragma unroll
                for (int mt = 0; mt < 2; ++mt)
                    mma_tf32(acc[mt][nt], a[mt][0], a[mt][1], a[mt][2], a[mt][3], bf0, bf1);
            }
        }
#pragma unroll
        for (int nt = 0; nt < 4; ++nt) {
            int col0 = warp * 32 + nt * 8 + tig * 2;
            float bb0 = fb1[band * 256 + col0];
            float bb1 = fb1[band * 256 + col0 + 1];
#pragma unroll
            for (int mt = 0; mt < 2; ++mt) {
                int r0 = mt * 16 + grp;
                us[r0 * UP + col0]           = f2tf_f(gelu_exact(acc[mt][nt][0] + bb0));
                us[r0 * UP + col0 + 1]       = f2tf_f(gelu_exact(acc[mt][nt][1] + bb1));
                us[(r0 + 8) * UP + col0]     = f2tf_f(gelu_exact(acc[mt][nt][2] + bb0));
                us[(r0 + 8) * UP + col0 + 1] = f2tf_f(gelu_exact(acc[mt][nt][3] + bb1));
            }
        }
    }
    __syncthreads();

    // ---- GEMM2: band_out = h + u @ W2 + b2 -> zs. FULL unroll ----
    {
        float acc[2][2][4];
#pragma unroll
        for (int mt = 0; mt < 2; ++mt)
#pragma unroll
            for (int nt = 0; nt < 2; ++nt)
#pragma unroll
                for (int c = 0; c < 4; ++c) acc[mt][nt][c] = 0.0f;

        const float* wbase = g_w2 + ((((size_t)band * 32) * 8 + warp) * 32 + lane) * 4;
        const float* u0 = us + grp * UP + tig;
#pragma unroll
        for (int kb = 0; kb < 32; ++kb) {
            const int k0 = kb * 8;
            uint32_t a[2][4];
#pragma unroll
            for (int mt = 0; mt < 2; ++mt) {
                const float* um = u0 + mt * 16 * UP + k0;
                a[mt][0] = __float_as_uint(um[0]);
                a[mt][1] = __float_as_uint(um[8 * UP]);
                a[mt][2] = __float_as_uint(um[4]);
                a[mt][3] = __float_as_uint(um[8 * UP + 4]);
            }
            const float4 wv = __ldg((const float4*)(wbase + (size_t)kb * 1024));
#pragma unroll
            for (int nt = 0; nt < 2; ++nt) {
                uint32_t bf0 = __float_as_uint(nt ? wv.z : wv.x);
                uint32_t bf1 = __float_as_uint(nt ? wv.w : wv.y);
#pragma unroll
                for (int mt = 0; mt < 2; ++mt)
                    mma_tf32(acc[mt][nt], a[mt][0], a[mt][1], a[mt][2], a[mt][3], bf0, bf1);
            }
        }
#pragma unroll
        for (int nt = 0; nt < 2; ++nt) {
            int col0 = warp * 16 + nt * 8 + tig * 2;
            float bb0 = fb2[band * 128 + col0];
            float bb1 = fb2[band * 128 + col0 + 1];
#pragma unroll
            for (int mt = 0; mt < 2; ++mt) {
                int r0 = mt * 16 + grp;
                zs[r0 * ZP + col0]           = f2tf_f(acc[mt][nt][0] + bb0 + hs[r0 * HP + col0]);
                zs[r0 * ZP + col0 + 1]       = f2tf_f(acc[mt][nt][1] + bb1 + hs[r0 * HP + col0 + 1]);
                zs[(r0 + 8) * ZP + col0]     = f2tf_f(acc[mt][nt][2] + bb0 + hs[(r0 + 8) * HP + col0]);
                zs[(r0 + 8) * ZP + col0 + 1] = f2tf_f(acc[mt][nt][3] + bb1 + hs[(r0 + 8) * HP + col0 + 1]);
            }
        }
    }
    __syncthreads();

    // ---- proj: p = band_out @ pw + pb -> g_p (tf32). FULL unroll ----
    {
        float acc[2][4];
#pragma unroll
        for (int mt = 0; mt < 2; ++mt)
#pragma unroll
            for (int c = 0; c < 4; ++c) acc[mt][c] = 0.0f;

        const float* wbase = g_wp + ((((size_t)band * 16) * 8 + warp) * 32 + lane) * 2;
        const float* z0 = zs + grp * ZP + tig;
#pragma unroll
        for (int kb = 0; kb < 16; ++kb) {
            const int k0 = kb * 8;
            uint32_t a[2][4];
#pragma unroll
            for (int mt = 0; mt < 2; ++mt) {
                const float* zm = z0 + mt * 16 * ZP + k0;
                a[mt][0] = __float_as_uint(zm[0]);
                a[mt][1] = __float_as_uint(zm[8 * ZP]);
                a[mt][2] = __float_as_uint(zm[4]);
                a[mt][3] = __float_as_uint(zm[8 * ZP + 4]);
            }
            const float2 wv = __ldg((const float2*)(wbase + (size_t)kb * 512));
            uint32_t bf0 = __float_as_uint(wv.x);
            uint32_t bf1 = __float_as_uint(wv.y);
#pragma unroll
            for (int mt = 0; mt < 2; ++mt)
                mma_tf32(acc[mt], a[mt][0], a[mt][1], a[mt][2], a[mt][3], bf0, bf1);
        }
        int col0 = warp * 8 + tig * 2;
        float bb0 = pb[band * 64 + col0];
        float bb1 = pb[band * 64 + col0 + 1];
#pragma unroll
        for (int mt = 0; mt < 2; ++mt) {
            int r0 = mt * 16 + grp;
            float2 v0 = make_float2(f2tf_f(acc[mt][0] + bb0), f2tf_f(acc[mt][1] + bb1));
            float2 v1 = make_float2(f2tf_f(acc[mt][2] + bb0), f2tf_f(acc[mt][3] + bb1));
            *(float2*)&g_p[(((size_t)b * T_ + t0 + r0) * NB_ + band) * 64 + col0] = v0;
            *(float2*)&g_p[(((size_t)b * T_ + t0 + r0 + 8) * NB_ + band) * 64 + col0] = v1;
        }
    }
}

// ---------------------------------------------------------------------------
// Kernel 3 (tensor-core GEMM1): cat[32,448] @ mix_w1 -> gelu -> fp32 128->16.
// FULL unroll (56 k-blocks, imm offsets). grid (B*T/32), block 256.
// ---------------------------------------------------------------------------
#define CP 452
#define MP 132

__global__ __launch_bounds__(256) void k_mix_tc(
    const float* __restrict__ mb1,
    const float* __restrict__ mw2, const float* __restrict__ mb2,
    float* __restrict__ out)
{
    extern __shared__ float sm[];
    float* cs = sm;                 // 32*452
    float* ms = sm + 32 * CP;       // 32*132

    const int bt0 = blockIdx.x * 32;
    const int tid = threadIdx.x;
    const int warp = tid >> 5, lane = tid & 31;
    const int grp = lane >> 2, tig = lane & 3;

    const float* cb = g_p + (size_t)bt0 * 448;
    for (int i = tid; i < 32 * 448; i += 256) {
        int r = i / 448, c = i - r * 448;
        cs[r * CP + c] = cb[i];
    }
    __syncthreads();

    {
        float acc[2][2][4];
#pragma unroll
        for (int mt = 0; mt < 2; ++mt)
#pragma unroll
            for (int nt = 0; nt < 2; ++nt)
#pragma unroll
                for (int c = 0; c < 4; ++c) acc[mt][nt][c] = 0.0f;

        const float* wbase = g_wm + ((size_t)warp * 32 + lane) * 4;
        const float* c0 = cs + grp * CP + tig;
#pragma unroll
        for (int kb = 0; kb < 56; ++kb) {
            const int k0 = kb * 8;
            uint32_t a[2][4];
#pragma unroll
            for (int mt = 0; mt < 2; ++mt) {
                const float* cm = c0 + mt * 16 * CP + k0;
                a[mt][0] = __float_as_uint(cm[0]);
                a[mt][1] = __float_as_uint(cm[8 * CP]);
                a[mt][2] = __float_as_uint(cm[4]);
                a[mt][3] = __float_as_uint(cm[8 * CP + 4]);
            }
            const float4 wv = __ldg((const float4*)(wbase + (size_t)kb * 1024));
#pragma unroll
            for (int nt = 0; nt < 2; ++nt) {
                uint32_t bf0 = __float_as_uint(nt ? wv.z : wv.x);
                uint32_t bf1 = __float_as_uint(nt ? wv.w : wv.y);
#pragma unroll
                for (int mt = 0; mt < 2; ++mt)
                    mma_tf32(acc[mt][nt], a[mt][0], a[mt][1], a[mt][2], a[mt][3], bf0, bf1);
            }
        }
#pragma unroll
        for (int nt = 0; nt < 2; ++nt) {
            int col0 = warp * 16 + nt * 8 + tig * 2;
            float bb0 = mb1[col0];
            float bb1 = mb1[col0 + 1];
#pragma unroll
            for (int mt = 0; mt < 2; ++mt) {
                int r0 = mt * 16 + grp;
                ms[r0 * MP + col0]           = gelu_exact(acc[mt][nt][0] + bb0);
                ms[r0 * MP + col0 + 1]       = gelu_exact(acc[mt][nt][1] + bb1);
                ms[(r0 + 8) * MP + col0]     = gelu_exact(acc[mt][nt][2] + bb0);
                ms[(r0 + 8) * MP + col0 + 1] = gelu_exact(acc[mt][nt][3] + bb1);
            }
        }
    }
    __syncthreads();

    {
        const int o = tid & 15, tb = tid >> 4;
        const float* wc = mw2 + o;
        const float bo = mb2[o];
#pragma unroll
        for (int h = 0; h < 2; ++h) {
            int tt = tb + h * 16;
            float acc = 0.0f;
#pragma unroll
            for (int e = 0; e < 128; e += 4) {
                float4 mv = *(const float4*)&ms[tt * MP + e];
                acc = fmaf(mv.x, wc[(e + 0) * 16], acc);
                acc = fmaf(mv.y, wc[(e + 1) * 16], acc);
                acc = fmaf(mv.z, wc[(e + 2) * 16], acc);
                acc = fmaf(mv.w, wc[(e + 3) * 16], acc);
            }
            out[(size_t)(bt0 + tt) * 16 + o] = acc + bo;
        }
    }
}

// ---------------------------------------------------------------------------
extern "C" void kernel_launch(void* const* d_in, const int* in_sizes, int n_in,
                              void* d_out, int out_size)
{
    const float* x      = (const float*)d_in[0];
    const float* conv_w = (const float*)d_in[1];
    const float* conv_b = (const float*)d_in[2];
    const float* dec_g  = (const float*)d_in[3];
    const float* dec_b  = (const float*)d_in[4];
    const float* n2_g   = (const float*)d_in[5];
    const float* n2_b   = (const float*)d_in[6];
    const float* ffn_w1 = (const float*)d_in[7];
    const float* ffn_b1 = (const float*)d_in[8];
    const float* ffn_w2 = (const float*)d_in[9];
    const float* ffn_b2 = (const float*)d_in[10];
    const float* proj_w = (const float*)d_in[11];
    const float* proj_b = (const float*)d_in[12];
    const float* mix_w1 = (const float*)d_in[13];
    const float* mix_b1 = (const float*)d_in[14];
    const float* mix_w2 = (const float*)d_in[15];
    const float* mix_b2 = (const float*)d_in[16];
    float* out = (float*)d_out;

    const int smem_fused = (8320 + 4224 + 4224) * 4;        // 67072 B
    const int smem_mix   = (32 * CP + 32 * MP) * 4;         // 74752 B
    cudaFuncSetAttribute(k_fused, cudaFuncAttributeMaxDynamicSharedMemorySize, smem_fused);
    cudaFuncSetAttribute(k_mix_tc, cudaFuncAttributeMaxDynamicSharedMemorySize, smem_mix);

    k_prep<<<512, 256>>>(conv_w, ffn_w1, ffn_w2, proj_w, mix_w1);

    dim3 g1(T_ / 32, B_, NB_);
    k_fused<<<g1, 256, smem_fused>>>(x, conv_b, dec_g, dec_b, n2_g, n2_b,
                                     ffn_b1, ffn_b2, proj_b);

    dim3 g3((B_ * T_) / 32);
    k_mix_tc<<<g3, 256, smem_mix>>>(mix_b1, mix_w2, mix_b2, out);
}